// round 13
// baseline (speedup 1.0000x reference)
#include <cuda_runtime.h>

#define NQ 22
#define DIM (1 << NQ)
#define NL 4
#define NB 1024   // grid blocks (10 block bits)

// State at PAIR granularity: float4 = (re0, im0, re1, im1) for amps (2p, 2p+1).
__device__ __align__(16) float4 g_state[DIM / 2];
__device__ float2 g_Ug[NL][NQ][4];   // fused RZ*RY*RX per (layer,qubit)
__device__ float  g_zpart[NB][13];   // per-block: z[amp0], z[amp1..11], T

// Bank swizzle over tile pair-index q: fold bits 3..5 into 0..2.
__device__ __forceinline__ int sig(int q) { return q ^ ((q >> 3) & 7); }

// Suffix parity: bit b -> parity(y_b..y_top). Inverse of XOR-shift CNOT perm.
__device__ __forceinline__ int sfx(int y) {
    y ^= y >> 1; y ^= y >> 2; y ^= y >> 4; y ^= y >> 8;
    return y;
}

struct C2 { float2 u00, u01, u10, u11; };

__device__ __forceinline__ C2 getU(int l, int q) {
    C2 c;
    c.u00 = g_Ug[l][q][0]; c.u01 = g_Ug[l][q][1];
    c.u10 = g_Ug[l][q][2]; c.u11 = g_Ug[l][q][3];
    return c;
}

// Complex 2x2 gate: x' = u00*x + u01*y ; y' = u10*x + u11*y
__device__ __forceinline__ void cgate(float2& x, float2& y, const C2& U) {
    float nxr = U.u00.x*x.x - U.u00.y*x.y + U.u01.x*y.x - U.u01.y*y.y;
    float nxi = U.u00.x*x.y + U.u00.y*x.x + U.u01.x*y.y + U.u01.y*y.x;
    float nyr = U.u10.x*x.x - U.u10.y*x.y + U.u11.x*y.x - U.u11.y*y.y;
    float nyi = U.u10.x*x.y + U.u10.y*x.x + U.u11.x*y.y + U.u11.y*y.x;
    x = make_float2(nxr, nxi);
    y = make_float2(nyr, nyi);
}

// Three gates on the s-bits of a[16] (a[2s],a[2s+1] = pair s).
__device__ __forceinline__ void gates3(float2 a[16], int l, int q0, int q1, int q2) {
    {
        C2 U = getU(l, q0);
#pragma unroll
        for (int s = 0; s < 8; s++) if (!(s & 1)) {
            cgate(a[2*s],   a[2*(s|1)],   U);
            cgate(a[2*s+1], a[2*(s|1)+1], U);
        }
    }
    {
        C2 U = getU(l, q1);
#pragma unroll
        for (int s = 0; s < 8; s++) if (!(s & 2)) {
            cgate(a[2*s],   a[2*(s|2)],   U);
            cgate(a[2*s+1], a[2*(s|2)+1], U);
        }
    }
    {
        C2 U = getU(l, q2);
#pragma unroll
        for (int s = 0; s < 8; s++) if (!(s & 4)) {
            cgate(a[2*s],   a[2*(s|4)],   U);
            cgate(a[2*s+1], a[2*(s|4)+1], U);
        }
    }
}

// Middle pass over 2048-pair tile (256 threads, 8 pairs/thread).
__device__ __forceinline__ void mid_pass(float4* sh4, int t, int pb,
                                         int q0, int q1, int q2, int l) {
    const int low = t & ((1 << pb) - 1);
    const int qbase = ((t >> pb) << (pb + 3)) | low;
    float2 a[16];
#pragma unroll
    for (int s = 0; s < 8; s++) {
        float4 v = sh4[sig(qbase | (s << pb))];
        a[2*s]   = make_float2(v.x, v.y);
        a[2*s+1] = make_float2(v.z, v.w);
    }
    gates3(a, l, q0, q1, q2);
#pragma unroll
    for (int s = 0; s < 8; s++) {
        sh4[sig(qbase | (s << pb))] =
            make_float4(a[2*s].x, a[2*s].y, a[2*s+1].x, a[2*s+1].y);
    }
}

// ---------------------------------------------------------------------------
// Fused single-qubit unitaries  U = RZ * RY * RX
// ---------------------------------------------------------------------------
__device__ __forceinline__ float2 cmulf(float2 a, float2 b) {
    return make_float2(a.x * b.x - a.y * b.y, a.x * b.y + a.y * b.x);
}

__global__ void make_gates(const float* __restrict__ params) {
    int t = threadIdx.x;
    if (t >= NL * NQ) return;
    int l = t / NQ, q = t % NQ;
    const float* p = params + (l * NQ + q) * 3;
    float tx = 0.5f * p[0], ty = 0.5f * p[1], tz = 0.5f * p[2];
    float cx = cosf(tx), sx = sinf(tx);
    float cy = cosf(ty), sy = sinf(ty);
    float cz = cosf(tz), sz = sinf(tz);
    float2 m00 = make_float2( cy * cx,  sy * sx);
    float2 m01 = make_float2(-sy * cx, -cy * sx);
    float2 m10 = make_float2( sy * cx, -cy * sx);
    float2 m11 = make_float2( cy * cx, -sy * sx);
    float2 e0 = make_float2(cz, -sz);
    float2 e1 = make_float2(cz,  sz);
    g_Ug[l][q][0] = cmulf(e0, m00);
    g_Ug[l][q][1] = cmulf(e0, m01);
    g_Ug[l][q][2] = cmulf(e1, m10);
    g_Ug[l][q][3] = cmulf(e1, m11);
}

// ---------------------------------------------------------------------------
// Kernel A: 2048-pair tile, pair bits = gp {0} U {11..20}.
//   q bit 0 = gp bit 0 (amp 1, coalescing); q bits 1..10 = gp bits 11..20
//   (amp bits 12..21 -> qubits 9..0: q bit j -> qubit 10-j). In-pair -> qubit 21.
//   gp = ((q>>1)<<11) | (blk<<1) | (q&1);  blk = gp bits 1..10.
// Pass1 (load, pb=1): intra 21 + qubits 9,8,7. Pass2 (pb=4): 6,5,4.
// Pass3 (pb=7): 3,2,1. Store pass (s = q bits 8..10): qubit 0 on s-bit 2,
//   scatter dest = (p&3) | (sfx(p)&0x7FC)  [inverse of CNOTs q=0..7].
// ---------------------------------------------------------------------------
__global__ void __launch_bounds__(256, 4)
layerA_kernel(int layer, const float* __restrict__ sre, const float* __restrict__ sim, int first) {
    extern __shared__ float4 sh4[];
    const int t = threadIdx.x;
    const int blk = blockIdx.x;

    float2 a[16];

    // ---- pass 1: global -> regs, intra 21 + gates 9,8,7, STS ----
    {
        const int qb = ((t >> 1) << 4) | (t & 1);
        if (first) {
#pragma unroll
            for (int s = 0; s < 8; s++) {
                int q = qb | (s << 1);
                int gp = ((q >> 1) << 11) | (blk << 1) | (q & 1);
                float2 r2 = *(const float2*)&sre[gp << 1];
                float2 i2 = *(const float2*)&sim[gp << 1];
                a[2*s]   = make_float2(r2.x, i2.x);
                a[2*s+1] = make_float2(r2.y, i2.y);
            }
        } else {
#pragma unroll
            for (int s = 0; s < 8; s++) {
                int q = qb | (s << 1);
                int gp = ((q >> 1) << 11) | (blk << 1) | (q & 1);
                float4 v = g_state[gp];
                a[2*s]   = make_float2(v.x, v.y);
                a[2*s+1] = make_float2(v.z, v.w);
            }
        }
        {
            C2 U = getU(layer, 21);
#pragma unroll
            for (int s = 0; s < 8; s++) cgate(a[2*s], a[2*s+1], U);
        }
        gates3(a, layer, 9, 8, 7);
#pragma unroll
        for (int s = 0; s < 8; s++) {
            sh4[sig(qb | (s << 1))] =
                make_float4(a[2*s].x, a[2*s].y, a[2*s+1].x, a[2*s+1].y);
        }
    }
    __syncthreads();

    mid_pass(sh4, t, 4, 6, 5, 4, layer);
    __syncthreads();
    mid_pass(sh4, t, 7, 3, 2, 1, layer);
    __syncthreads();

    // ---- store pass: LDS (s = q bits 8..10), gate qubit 0 on s-bit 2, scatter ----
    {
#pragma unroll
        for (int s = 0; s < 8; s++) {
            float4 v = sh4[sig(t | (s << 8))];
            a[2*s]   = make_float2(v.x, v.y);
            a[2*s+1] = make_float2(v.z, v.w);
        }
        {
            C2 U = getU(layer, 0);
#pragma unroll
            for (int s = 0; s < 8; s++) if (!(s & 4)) {
                cgate(a[2*s],   a[2*(s|4)],   U);
                cgate(a[2*s+1], a[2*(s|4)+1], U);
            }
        }
        const int dA = (t & 3) | (sfx(t) & 0x7FC);
#pragma unroll
        for (int s = 0; s < 8; s++) {
            int dest = dA ^ (sfx(s << 8) & 0x7FC);
            int gp = ((dest >> 1) << 11) | (blk << 1) | (dest & 1);
            g_state[gp] = make_float4(a[2*s].x, a[2*s].y, a[2*s+1].x, a[2*s+1].y);
        }
    }
}

// ---------------------------------------------------------------------------
// Kernel B body: contiguous 2048-pair tile (pair base = blk<<11).
//   q bit j = amp bit j+1 -> qubit 20-j. Gates qubits 10..20 (no intra).
// Pass1 (load, pb=0): 20,19,18. Pass2 (pb=3): 17,16,15. Pass3 (pb=6): 14,13,12.
// Store pass (s = q bits 8..10): qubits 11 (s-bit 1), 10 (s-bit 2).
// Leaves final a[16] in registers (post all gates).
// ---------------------------------------------------------------------------
__device__ __forceinline__ void layerB_body(float4* sh4, float2 a[16], int t,
                                            int base, int layer) {
    {
        const int qb = t << 3;
#pragma unroll
        for (int s = 0; s < 8; s++) {
            float4 v = g_state[base + (qb | s)];
            a[2*s]   = make_float2(v.x, v.y);
            a[2*s+1] = make_float2(v.z, v.w);
        }
        gates3(a, layer, 20, 19, 18);
#pragma unroll
        for (int s = 0; s < 8; s++) {
            sh4[sig(qb | s)] =
                make_float4(a[2*s].x, a[2*s].y, a[2*s+1].x, a[2*s+1].y);
        }
    }
    __syncthreads();
    mid_pass(sh4, t, 3, 17, 16, 15, layer);
    __syncthreads();
    mid_pass(sh4, t, 6, 14, 13, 12, layer);
    __syncthreads();
#pragma unroll
    for (int s = 0; s < 8; s++) {
        float4 v = sh4[sig(t | (s << 8))];
        a[2*s]   = make_float2(v.x, v.y);
        a[2*s+1] = make_float2(v.z, v.w);
    }
    {
        C2 U = getU(layer, 11);
#pragma unroll
        for (int s = 0; s < 8; s++) if (!(s & 2)) {
            cgate(a[2*s],   a[2*(s|2)],   U);
            cgate(a[2*s+1], a[2*(s|2)+1], U);
        }
    }
    {
        C2 U = getU(layer, 10);
#pragma unroll
        for (int s = 0; s < 8; s++) if (!(s & 4)) {
            cgate(a[2*s],   a[2*(s|4)],   U);
            cgate(a[2*s+1], a[2*(s|4)+1], U);
        }
    }
}

// ---------------------------------------------------------------------------
// Kernel B (layers 0..2): store path. CNOTs q=8..20 flip amp bits 0..12 with
// the bit above. In-tile: dest = sfx(q) ^ (bb ? 0x7FF : 0), bb = blk0^blk1;
// dest block: dblk = blk with bit0 ^= bit1 (cross-block scatter);
// half-swap iff dest odd.
// ---------------------------------------------------------------------------
__global__ void __launch_bounds__(256, 4)
layerB_kernel(int layer) {
    extern __shared__ float4 sh4[];
    const int t = threadIdx.x;
    const int blk = blockIdx.x;
    const int base = blk << 11;

    float2 a[16];
    layerB_body(sh4, a, t, base, layer);

    const int sfxt = sfx(t);
    const int bb = (blk ^ (blk >> 1)) & 1;
    const int BB = bb ? 0x7FF : 0;
    const int dbase = (blk ^ ((blk >> 1) & 1)) << 11;
#pragma unroll
    for (int s = 0; s < 8; s++) {
        int dest = sfxt ^ sfx(s << 8) ^ BB;
        float4 v = make_float4(a[2*s].x, a[2*s].y, a[2*s+1].x, a[2*s+1].y);
        if (dest & 1) v = make_float4(v.z, v.w, v.x, v.y);
        g_state[dbase + dest] = v;
    }
}

// ---------------------------------------------------------------------------
// Kernel B last layer: fused <Z> epilogue, no store.
// Final amp: bit0 = c ^ dest0; bits 1..11 = dest; bit12 = blk0^blk1;
// bits 13..21 = blk bits 1..9.  dest = sfx(t)^sfx(s<<8)^BB:
// dest bits 0..8 flip with par(s); bit 9 with s1^s2; bit 10 with s2.
// ---------------------------------------------------------------------------
__global__ void __launch_bounds__(256, 4)
layerB_last_kernel(int layer) {
    extern __shared__ float4 sh4[];
    const int t = threadIdx.x;
    const int blk = blockIdx.x;
    const int base = blk << 11;

    float2 a[16];
    layerB_body(sh4, a, t, base, layer);

    const int sfxt = sfx(t);
    const int bb = (blk ^ (blk >> 1)) & 1;

    float S00 = 0.f, S01 = 0.f, S10 = 0.f, S11 = 0.f, W9 = 0.f, W10 = 0.f;
#pragma unroll
    for (int s = 0; s < 8; s++) {
        float2 x0 = a[2*s], x1 = a[2*s+1];
        float p0 = fmaf(x0.x, x0.x, x0.y * x0.y);
        float p1 = fmaf(x1.x, x1.x, x1.y * x1.y);
        bool par = (0x96 >> s) & 1;          // parity(s)
        if (par) { S10 += p0; S11 += p1; }
        else     { S00 += p0; S01 += p1; }
        float ps = p0 + p1;
        W9  += ((0x3C >> s) & 1) ? -ps : ps; // s1^s2
        W10 += (s & 4) ? -ps : ps;           // s2
    }
    float Se = S00 + S01, So = S10 + S11;
    float T  = Se + So;
    float E  = Se - So;

    float z[13];
    {
        float z0 = (S00 - S01) - (S10 - S11);
        z[0] = (((sfxt ^ bb) & 1)) ? -z0 : z0;          // amp bit 0 (qubit 21)
    }
#pragma unroll
    for (int d = 0; d < 9; d++)                          // amp bits 1..9
        z[d + 1] = ((((sfxt >> d) ^ bb) & 1)) ? -E : E;
    z[10] = bb ? -W9  : W9;                              // amp bit 10 (dest bit 9)
    z[11] = bb ? -W10 : W10;                             // amp bit 11 (dest bit 10)
    z[12] = T;

    __shared__ float wsum[13][9];
    int lane = t & 31, wp = t >> 5;
#pragma unroll
    for (int b = 0; b < 13; b++) {
        float v = z[b];
        for (int off = 16; off; off >>= 1) v += __shfl_xor_sync(0xffffffffu, v, off);
        if (lane == 0) wsum[b][wp] = v;
    }
    __syncthreads();
    if (t < 13) {
        float sacc = 0.f;
        for (int w = 0; w < 8; w++) sacc += wsum[t][w];
        g_zpart[blk][t] = sacc;
    }
}

// ---------------------------------------------------------------------------
// Final reduce: warp w handles qubit w (amp bit b = 21-w). 1024 block partials,
// 32 per lane; warp-shuffle reduce; divide by norm^2 (= total T).
// amp bit 12 sign = blk0^blk1; amp bits 13..21 sign = blk bits 1..9.
// ---------------------------------------------------------------------------
__global__ void final_reduce(float* __restrict__ out) {
    int w = threadIdx.x >> 5;
    int lane = threadIdx.x & 31;
    if (w >= 22) return;
    int b = 21 - w;
    float s = 0.f, tot = 0.f;
#pragma unroll
    for (int k = 0; k < 32; k++) {
        int i = lane + k * 32;
        float Ti = g_zpart[i][12];
        tot += Ti;
        if (b < 12)       s += g_zpart[i][b];
        else if (b == 12) s += (((i ^ (i >> 1)) & 1)) ? -Ti : Ti;
        else              s += (((i >> (b - 12)) & 1)) ? -Ti : Ti;
    }
    for (int off = 16; off; off >>= 1) {
        s   += __shfl_xor_sync(0xffffffffu, s, off);
        tot += __shfl_xor_sync(0xffffffffu, tot, off);
    }
    if (lane == 0) out[w] = s / tot;
}

// ---------------------------------------------------------------------------
extern "C" void kernel_launch(void* const* d_in, const int* in_sizes, int n_in,
                              void* d_out, int out_size) {
    const float* params = (const float*)d_in[0];
    const float* re     = (const float*)d_in[1];
    const float* im     = (const float*)d_in[2];
    float* out = (float*)d_out;

    cudaFuncSetAttribute(layerA_kernel, cudaFuncAttributeMaxDynamicSharedMemorySize, 32768);
    cudaFuncSetAttribute(layerB_kernel, cudaFuncAttributeMaxDynamicSharedMemorySize, 32768);
    cudaFuncSetAttribute(layerB_last_kernel, cudaFuncAttributeMaxDynamicSharedMemorySize, 32768);

    make_gates<<<1, 128>>>(params);
    for (int l = 0; l < NL; l++) {
        layerA_kernel<<<NB, 256, 32768>>>(l, re, im, l == 0 ? 1 : 0);
        if (l < NL - 1) layerB_kernel<<<NB, 256, 32768>>>(l);
        else            layerB_last_kernel<<<NB, 256, 32768>>>(l);
    }
    final_reduce<<<1, 704>>>(out);
}

// round 14
// speedup vs baseline: 1.0009x; 1.0009x over previous
#include <cuda_runtime.h>

#define NQ 22
#define DIM (1 << NQ)
#define NL 4
#define NB 1024   // grid blocks (10 block bits)

// State at PAIR granularity: float4 = (re0, im0, re1, im1) for amps (2p, 2p+1).
__device__ __align__(16) float4 g_state[DIM / 2];
__device__ float2 g_Ug[NL][NQ][4];   // fused RZ*RY*RX per (layer,qubit)
__device__ float  g_zpart[NB][13];   // per-block: z[amp0], z[amp1..11], T

// Bank swizzle over tile pair-index q: fold bits 3..5 into 0..2.
__device__ __forceinline__ int sig(int q) { return q ^ ((q >> 3) & 7); }

// Suffix parity: bit b -> parity(y_b..y_top). Inverse of XOR-shift CNOT perm.
__device__ __forceinline__ int sfx(int y) {
    y ^= y >> 1; y ^= y >> 2; y ^= y >> 4; y ^= y >> 8;
    return y;
}

struct C2 { float2 u00, u01, u10, u11; };

__device__ __forceinline__ C2 getU(int l, int q) {
    C2 c;
    c.u00 = g_Ug[l][q][0]; c.u01 = g_Ug[l][q][1];
    c.u10 = g_Ug[l][q][2]; c.u11 = g_Ug[l][q][3];
    return c;
}

// Complex 2x2 gate: x' = u00*x + u01*y ; y' = u10*x + u11*y
__device__ __forceinline__ void cgate(float2& x, float2& y, const C2& U) {
    float nxr = U.u00.x*x.x - U.u00.y*x.y + U.u01.x*y.x - U.u01.y*y.y;
    float nxi = U.u00.x*x.y + U.u00.y*x.x + U.u01.x*y.y + U.u01.y*y.x;
    float nyr = U.u10.x*x.x - U.u10.y*x.y + U.u11.x*y.x - U.u11.y*y.y;
    float nyi = U.u10.x*x.y + U.u10.y*x.x + U.u11.x*y.y + U.u11.y*y.x;
    x = make_float2(nxr, nxi);
    y = make_float2(nyr, nyi);
}

// Three gates on the s-bits of a[16] (a[2s],a[2s+1] = pair s).
__device__ __forceinline__ void gates3(float2 a[16], int l, int q0, int q1, int q2) {
    {
        C2 U = getU(l, q0);
#pragma unroll
        for (int s = 0; s < 8; s++) if (!(s & 1)) {
            cgate(a[2*s],   a[2*(s|1)],   U);
            cgate(a[2*s+1], a[2*(s|1)+1], U);
        }
    }
    {
        C2 U = getU(l, q1);
#pragma unroll
        for (int s = 0; s < 8; s++) if (!(s & 2)) {
            cgate(a[2*s],   a[2*(s|2)],   U);
            cgate(a[2*s+1], a[2*(s|2)+1], U);
        }
    }
    {
        C2 U = getU(l, q2);
#pragma unroll
        for (int s = 0; s < 8; s++) if (!(s & 4)) {
            cgate(a[2*s],   a[2*(s|4)],   U);
            cgate(a[2*s+1], a[2*(s|4)+1], U);
        }
    }
}

// Middle pass over 2048-pair tile (256 threads, 8 pairs/thread).
__device__ __forceinline__ void mid_pass(float4* sh4, int t, int pb,
                                         int q0, int q1, int q2, int l) {
    const int low = t & ((1 << pb) - 1);
    const int qbase = ((t >> pb) << (pb + 3)) | low;
    float2 a[16];
#pragma unroll
    for (int s = 0; s < 8; s++) {
        float4 v = sh4[sig(qbase | (s << pb))];
        a[2*s]   = make_float2(v.x, v.y);
        a[2*s+1] = make_float2(v.z, v.w);
    }
    gates3(a, l, q0, q1, q2);
#pragma unroll
    for (int s = 0; s < 8; s++) {
        sh4[sig(qbase | (s << pb))] =
            make_float4(a[2*s].x, a[2*s].y, a[2*s+1].x, a[2*s+1].y);
    }
}

// ---------------------------------------------------------------------------
// Fused single-qubit unitaries  U = RZ * RY * RX
// ---------------------------------------------------------------------------
__device__ __forceinline__ float2 cmulf(float2 a, float2 b) {
    return make_float2(a.x * b.x - a.y * b.y, a.x * b.y + a.y * b.x);
}

__global__ void make_gates(const float* __restrict__ params) {
    int t = threadIdx.x;
    if (t >= NL * NQ) return;
    int l = t / NQ, q = t % NQ;
    const float* p = params + (l * NQ + q) * 3;
    float tx = 0.5f * p[0], ty = 0.5f * p[1], tz = 0.5f * p[2];
    float cx = cosf(tx), sx = sinf(tx);
    float cy = cosf(ty), sy = sinf(ty);
    float cz = cosf(tz), sz = sinf(tz);
    float2 m00 = make_float2( cy * cx,  sy * sx);
    float2 m01 = make_float2(-sy * cx, -cy * sx);
    float2 m10 = make_float2( sy * cx, -cy * sx);
    float2 m11 = make_float2( cy * cx, -sy * sx);
    float2 e0 = make_float2(cz, -sz);
    float2 e1 = make_float2(cz,  sz);
    g_Ug[l][q][0] = cmulf(e0, m00);
    g_Ug[l][q][1] = cmulf(e0, m01);
    g_Ug[l][q][2] = cmulf(e1, m10);
    g_Ug[l][q][3] = cmulf(e1, m11);
}

// ---------------------------------------------------------------------------
// Kernel A: 2048-pair tile, pair bits = gp {0} U {11..20}.
//   q bit 0 = gp bit 0 (amp 1, coalescing); q bits 1..10 = gp bits 11..20
//   (amp bits 12..21 -> qubits 9..0: q bit j -> qubit 10-j). In-pair -> qubit 21.
//   gp = ((q>>1)<<11) | (blk<<1) | (q&1);  blk = gp bits 1..10.
// Pass1 (load, pb=1): intra 21 + qubits 9,8,7. Pass2 (pb=4): 6,5,4.
// Pass3 (pb=7): 3,2,1. Store pass (s = q bits 8..10): qubit 0 on s-bit 2,
//   scatter dest = (p&3) | (sfx(p)&0x7FC)  [inverse of CNOTs q=0..7].
// ---------------------------------------------------------------------------
__global__ void __launch_bounds__(256, 4)
layerA_kernel(int layer, const float* __restrict__ sre, const float* __restrict__ sim, int first) {
    extern __shared__ float4 sh4[];
    const int t = threadIdx.x;
    const int blk = blockIdx.x;

    float2 a[16];

    // ---- pass 1: global -> regs, intra 21 + gates 9,8,7, STS ----
    {
        const int qb = ((t >> 1) << 4) | (t & 1);
        if (first) {
#pragma unroll
            for (int s = 0; s < 8; s++) {
                int q = qb | (s << 1);
                int gp = ((q >> 1) << 11) | (blk << 1) | (q & 1);
                float2 r2 = *(const float2*)&sre[gp << 1];
                float2 i2 = *(const float2*)&sim[gp << 1];
                a[2*s]   = make_float2(r2.x, i2.x);
                a[2*s+1] = make_float2(r2.y, i2.y);
            }
        } else {
#pragma unroll
            for (int s = 0; s < 8; s++) {
                int q = qb | (s << 1);
                int gp = ((q >> 1) << 11) | (blk << 1) | (q & 1);
                float4 v = g_state[gp];
                a[2*s]   = make_float2(v.x, v.y);
                a[2*s+1] = make_float2(v.z, v.w);
            }
        }
        {
            C2 U = getU(layer, 21);
#pragma unroll
            for (int s = 0; s < 8; s++) cgate(a[2*s], a[2*s+1], U);
        }
        gates3(a, layer, 9, 8, 7);
#pragma unroll
        for (int s = 0; s < 8; s++) {
            sh4[sig(qb | (s << 1))] =
                make_float4(a[2*s].x, a[2*s].y, a[2*s+1].x, a[2*s+1].y);
        }
    }
    __syncthreads();

    mid_pass(sh4, t, 4, 6, 5, 4, layer);
    __syncthreads();
    mid_pass(sh4, t, 7, 3, 2, 1, layer);
    __syncthreads();

    // ---- store pass: LDS (s = q bits 8..10), gate qubit 0 on s-bit 2, scatter ----
    {
#pragma unroll
        for (int s = 0; s < 8; s++) {
            float4 v = sh4[sig(t | (s << 8))];
            a[2*s]   = make_float2(v.x, v.y);
            a[2*s+1] = make_float2(v.z, v.w);
        }
        {
            C2 U = getU(layer, 0);
#pragma unroll
            for (int s = 0; s < 8; s++) if (!(s & 4)) {
                cgate(a[2*s],   a[2*(s|4)],   U);
                cgate(a[2*s+1], a[2*(s|4)+1], U);
            }
        }
        const int dA = (t & 3) | (sfx(t) & 0x7FC);
#pragma unroll
        for (int s = 0; s < 8; s++) {
            int dest = dA ^ (sfx(s << 8) & 0x7FC);
            int gp = ((dest >> 1) << 11) | (blk << 1) | (dest & 1);
            g_state[gp] = make_float4(a[2*s].x, a[2*s].y, a[2*s+1].x, a[2*s+1].y);
        }
    }
}

// ---------------------------------------------------------------------------
// Kernel B body: contiguous 2048-pair tile (pair base = blk<<11).
//   q bit j = amp bit j+1 -> qubit 20-j. Gates qubits 10..20 (no intra).
// Pass1 (load, pb=0): 20,19,18. Pass2 (pb=3): 17,16,15. Pass3 (pb=6): 14,13,12.
// Store pass (s = q bits 8..10): qubits 11 (s-bit 1), 10 (s-bit 2).
// Leaves final a[16] in registers (post all gates).
// ---------------------------------------------------------------------------
__device__ __forceinline__ void layerB_body(float4* sh4, float2 a[16], int t,
                                            int base, int layer) {
    {
        const int qb = t << 3;
#pragma unroll
        for (int s = 0; s < 8; s++) {
            float4 v = g_state[base + (qb | s)];
            a[2*s]   = make_float2(v.x, v.y);
            a[2*s+1] = make_float2(v.z, v.w);
        }
        gates3(a, layer, 20, 19, 18);
#pragma unroll
        for (int s = 0; s < 8; s++) {
            sh4[sig(qb | s)] =
                make_float4(a[2*s].x, a[2*s].y, a[2*s+1].x, a[2*s+1].y);
        }
    }
    __syncthreads();
    mid_pass(sh4, t, 3, 17, 16, 15, layer);
    __syncthreads();
    mid_pass(sh4, t, 6, 14, 13, 12, layer);
    __syncthreads();
#pragma unroll
    for (int s = 0; s < 8; s++) {
        float4 v = sh4[sig(t | (s << 8))];
        a[2*s]   = make_float2(v.x, v.y);
        a[2*s+1] = make_float2(v.z, v.w);
    }
    {
        C2 U = getU(layer, 11);
#pragma unroll
        for (int s = 0; s < 8; s++) if (!(s & 2)) {
            cgate(a[2*s],   a[2*(s|2)],   U);
            cgate(a[2*s+1], a[2*(s|2)+1], U);
        }
    }
    {
        C2 U = getU(layer, 10);
#pragma unroll
        for (int s = 0; s < 8; s++) if (!(s & 4)) {
            cgate(a[2*s],   a[2*(s|4)],   U);
            cgate(a[2*s+1], a[2*(s|4)+1], U);
        }
    }
}

// ---------------------------------------------------------------------------
// Kernel B (layers 0..2): store path. CNOTs q=8..20 flip amp bits 0..12 with
// the bit above. In-tile: dest = sfx(q) ^ (bb ? 0x7FF : 0), bb = blk0^blk1;
// dest block: dblk = blk with bit0 ^= bit1 (cross-block scatter);
// half-swap iff dest odd.
// ---------------------------------------------------------------------------
__global__ void __launch_bounds__(256, 4)
layerB_kernel(int layer) {
    extern __shared__ float4 sh4[];
    const int t = threadIdx.x;
    const int blk = blockIdx.x;
    const int base = blk << 11;

    float2 a[16];
    layerB_body(sh4, a, t, base, layer);

    const int sfxt = sfx(t);
    const int bb = (blk ^ (blk >> 1)) & 1;
    const int BB = bb ? 0x7FF : 0;
    const int dbase = (blk ^ ((blk >> 1) & 1)) << 11;
#pragma unroll
    for (int s = 0; s < 8; s++) {
        int dest = sfxt ^ sfx(s << 8) ^ BB;
        float4 v = make_float4(a[2*s].x, a[2*s].y, a[2*s+1].x, a[2*s+1].y);
        if (dest & 1) v = make_float4(v.z, v.w, v.x, v.y);
        g_state[dbase + dest] = v;
    }
}

// ---------------------------------------------------------------------------
// Kernel B last layer: fused <Z> epilogue, no store.
// Final amp: bit0 = c ^ dest0; bits 1..11 = dest; bit12 = blk0^blk1;
// bits 13..21 = blk bits 1..9.  dest = sfx(t)^sfx(s<<8)^BB:
// dest bits 0..8 flip with par(s); bit 9 with s1^s2; bit 10 with s2.
// ---------------------------------------------------------------------------
__global__ void __launch_bounds__(256, 4)
layerB_last_kernel(int layer) {
    extern __shared__ float4 sh4[];
    const int t = threadIdx.x;
    const int blk = blockIdx.x;
    const int base = blk << 11;

    float2 a[16];
    layerB_body(sh4, a, t, base, layer);

    const int sfxt = sfx(t);
    const int bb = (blk ^ (blk >> 1)) & 1;

    float S00 = 0.f, S01 = 0.f, S10 = 0.f, S11 = 0.f, W9 = 0.f, W10 = 0.f;
#pragma unroll
    for (int s = 0; s < 8; s++) {
        float2 x0 = a[2*s], x1 = a[2*s+1];
        float p0 = fmaf(x0.x, x0.x, x0.y * x0.y);
        float p1 = fmaf(x1.x, x1.x, x1.y * x1.y);
        bool par = (0x96 >> s) & 1;          // parity(s)
        if (par) { S10 += p0; S11 += p1; }
        else     { S00 += p0; S01 += p1; }
        float ps = p0 + p1;
        W9  += ((0x3C >> s) & 1) ? -ps : ps; // s1^s2
        W10 += (s & 4) ? -ps : ps;           // s2
    }
    float Se = S00 + S01, So = S10 + S11;
    float T  = Se + So;
    float E  = Se - So;

    float z[13];
    {
        float z0 = (S00 - S01) - (S10 - S11);
        z[0] = (((sfxt ^ bb) & 1)) ? -z0 : z0;          // amp bit 0 (qubit 21)
    }
#pragma unroll
    for (int d = 0; d < 9; d++)                          // amp bits 1..9
        z[d + 1] = ((((sfxt >> d) ^ bb) & 1)) ? -E : E;
    z[10] = bb ? -W9  : W9;                              // amp bit 10 (dest bit 9)
    z[11] = bb ? -W10 : W10;                             // amp bit 11 (dest bit 10)
    z[12] = T;

    __shared__ float wsum[13][9];
    int lane = t & 31, wp = t >> 5;
#pragma unroll
    for (int b = 0; b < 13; b++) {
        float v = z[b];
        for (int off = 16; off; off >>= 1) v += __shfl_xor_sync(0xffffffffu, v, off);
        if (lane == 0) wsum[b][wp] = v;
    }
    __syncthreads();
    if (t < 13) {
        float sacc = 0.f;
        for (int w = 0; w < 8; w++) sacc += wsum[t][w];
        g_zpart[blk][t] = sacc;
    }
}

// ---------------------------------------------------------------------------
// Final reduce: warp w handles qubit w (amp bit b = 21-w). 1024 block partials,
// 32 per lane; warp-shuffle reduce; divide by norm^2 (= total T).
// amp bit 12 sign = blk0^blk1; amp bits 13..21 sign = blk bits 1..9.
// ---------------------------------------------------------------------------
__global__ void final_reduce(float* __restrict__ out) {
    int w = threadIdx.x >> 5;
    int lane = threadIdx.x & 31;
    if (w >= 22) return;
    int b = 21 - w;
    float s = 0.f, tot = 0.f;
#pragma unroll
    for (int k = 0; k < 32; k++) {
        int i = lane + k * 32;
        float Ti = g_zpart[i][12];
        tot += Ti;
        if (b < 12)       s += g_zpart[i][b];
        else if (b == 12) s += (((i ^ (i >> 1)) & 1)) ? -Ti : Ti;
        else              s += (((i >> (b - 12)) & 1)) ? -Ti : Ti;
    }
    for (int off = 16; off; off >>= 1) {
        s   += __shfl_xor_sync(0xffffffffu, s, off);
        tot += __shfl_xor_sync(0xffffffffu, tot, off);
    }
    if (lane == 0) out[w] = s / tot;
}

// ---------------------------------------------------------------------------
extern "C" void kernel_launch(void* const* d_in, const int* in_sizes, int n_in,
                              void* d_out, int out_size) {
    const float* params = (const float*)d_in[0];
    const float* re     = (const float*)d_in[1];
    const float* im     = (const float*)d_in[2];
    float* out = (float*)d_out;

    cudaFuncSetAttribute(layerA_kernel, cudaFuncAttributeMaxDynamicSharedMemorySize, 32768);
    cudaFuncSetAttribute(layerB_kernel, cudaFuncAttributeMaxDynamicSharedMemorySize, 32768);
    cudaFuncSetAttribute(layerB_last_kernel, cudaFuncAttributeMaxDynamicSharedMemorySize, 32768);

    make_gates<<<1, 128>>>(params);
    for (int l = 0; l < NL; l++) {
        layerA_kernel<<<NB, 256, 32768>>>(l, re, im, l == 0 ? 1 : 0);
        if (l < NL - 1) layerB_kernel<<<NB, 256, 32768>>>(l);
        else            layerB_last_kernel<<<NB, 256, 32768>>>(l);
    }
    final_reduce<<<1, 704>>>(out);
}

// round 15
// speedup vs baseline: 1.0029x; 1.0020x over previous
#include <cuda_runtime.h>

#define NQ 22
#define DIM (1 << NQ)
#define NL 4
#define NB 1024   // grid blocks (10 block bits)

// State at PAIR granularity: float4 = (re0, im0, re1, im1) for amps (2p, 2p+1).
__device__ __align__(16) float4 g_state[DIM / 2];
__device__ float2 g_Ug[NL][NQ][4];   // fused RZ*RY*RX per (layer,qubit)
__device__ float  g_zpart[NB][13];   // per-block: z[amp0], z[amp1..11], T

// Bank swizzle over tile pair-index q: fold bits 3..5 into 0..2.
__device__ __forceinline__ int sig(int q) { return q ^ ((q >> 3) & 7); }

// Suffix parity: bit b -> parity(y_b..y_top). Inverse of XOR-shift CNOT perm.
__device__ __forceinline__ int sfx(int y) {
    y ^= y >> 1; y ^= y >> 2; y ^= y >> 4; y ^= y >> 8;
    return y;
}

struct C2 { float2 u00, u01, u10, u11; };

__device__ __forceinline__ C2 getU(int l, int q) {
    C2 c;
    c.u00 = g_Ug[l][q][0]; c.u01 = g_Ug[l][q][1];
    c.u10 = g_Ug[l][q][2]; c.u11 = g_Ug[l][q][3];
    return c;
}

// Complex 2x2 gate: x' = u00*x + u01*y ; y' = u10*x + u11*y
__device__ __forceinline__ void cgate(float2& x, float2& y, const C2& U) {
    float nxr = U.u00.x*x.x - U.u00.y*x.y + U.u01.x*y.x - U.u01.y*y.y;
    float nxi = U.u00.x*x.y + U.u00.y*x.x + U.u01.x*y.y + U.u01.y*y.x;
    float nyr = U.u10.x*x.x - U.u10.y*x.y + U.u11.x*y.x - U.u11.y*y.y;
    float nyi = U.u10.x*x.y + U.u10.y*x.x + U.u11.x*y.y + U.u11.y*y.x;
    x = make_float2(nxr, nxi);
    y = make_float2(nyr, nyi);
}

// Three gates on the s-bits of a[16] (a[2s],a[2s+1] = pair s).
__device__ __forceinline__ void gates3(float2 a[16], int l, int q0, int q1, int q2) {
    {
        C2 U = getU(l, q0);
#pragma unroll
        for (int s = 0; s < 8; s++) if (!(s & 1)) {
            cgate(a[2*s],   a[2*(s|1)],   U);
            cgate(a[2*s+1], a[2*(s|1)+1], U);
        }
    }
    {
        C2 U = getU(l, q1);
#pragma unroll
        for (int s = 0; s < 8; s++) if (!(s & 2)) {
            cgate(a[2*s],   a[2*(s|2)],   U);
            cgate(a[2*s+1], a[2*(s|2)+1], U);
        }
    }
    {
        C2 U = getU(l, q2);
#pragma unroll
        for (int s = 0; s < 8; s++) if (!(s & 4)) {
            cgate(a[2*s],   a[2*(s|4)],   U);
            cgate(a[2*s+1], a[2*(s|4)+1], U);
        }
    }
}

// Middle pass over 2048-pair tile (256 threads, 8 pairs/thread).
__device__ __forceinline__ void mid_pass(float4* sh4, int t, int pb,
                                         int q0, int q1, int q2, int l) {
    const int low = t & ((1 << pb) - 1);
    const int qbase = ((t >> pb) << (pb + 3)) | low;
    float2 a[16];
#pragma unroll
    for (int s = 0; s < 8; s++) {
        float4 v = sh4[sig(qbase | (s << pb))];
        a[2*s]   = make_float2(v.x, v.y);
        a[2*s+1] = make_float2(v.z, v.w);
    }
    gates3(a, l, q0, q1, q2);
#pragma unroll
    for (int s = 0; s < 8; s++) {
        sh4[sig(qbase | (s << pb))] =
            make_float4(a[2*s].x, a[2*s].y, a[2*s+1].x, a[2*s+1].y);
    }
}

// ---------------------------------------------------------------------------
// Fused single-qubit unitaries  U = RZ * RY * RX
// ---------------------------------------------------------------------------
__device__ __forceinline__ float2 cmulf(float2 a, float2 b) {
    return make_float2(a.x * b.x - a.y * b.y, a.x * b.y + a.y * b.x);
}

__global__ void make_gates(const float* __restrict__ params) {
    int t = threadIdx.x;
    if (t >= NL * NQ) return;
    int l = t / NQ, q = t % NQ;
    const float* p = params + (l * NQ + q) * 3;
    float tx = 0.5f * p[0], ty = 0.5f * p[1], tz = 0.5f * p[2];
    float cx = cosf(tx), sx = sinf(tx);
    float cy = cosf(ty), sy = sinf(ty);
    float cz = cosf(tz), sz = sinf(tz);
    float2 m00 = make_float2( cy * cx,  sy * sx);
    float2 m01 = make_float2(-sy * cx, -cy * sx);
    float2 m10 = make_float2( sy * cx, -cy * sx);
    float2 m11 = make_float2( cy * cx, -sy * sx);
    float2 e0 = make_float2(cz, -sz);
    float2 e1 = make_float2(cz,  sz);
    g_Ug[l][q][0] = cmulf(e0, m00);
    g_Ug[l][q][1] = cmulf(e0, m01);
    g_Ug[l][q][2] = cmulf(e1, m10);
    g_Ug[l][q][3] = cmulf(e1, m11);
}

// ---------------------------------------------------------------------------
// Kernel A: 2048-pair tile, pair bits = gp {0} U {11..20}.
//   q bit 0 = gp bit 0 (amp 1, coalescing); q bits 1..10 = gp bits 11..20
//   (amp bits 12..21 -> qubits 9..0: q bit j -> qubit 10-j). In-pair -> qubit 21.
//   gp = ((q>>1)<<11) | (blk<<1) | (q&1);  blk = gp bits 1..10.
// Pass1 (load, pb=1): intra 21 + qubits 9,8,7. Pass2 (pb=4): 6,5,4.
// Pass3 (pb=7): 3,2,1. Store pass (s = q bits 8..10): qubit 0 on s-bit 2,
//   scatter dest = (p&3) | (sfx(p)&0x7FC)  [inverse of CNOTs q=0..7].
// ---------------------------------------------------------------------------
__global__ void __launch_bounds__(256, 4)
layerA_kernel(int layer, const float* __restrict__ sre, const float* __restrict__ sim, int first) {
    extern __shared__ float4 sh4[];
    const int t = threadIdx.x;
    const int blk = blockIdx.x;

    float2 a[16];

    // ---- pass 1: global -> regs, intra 21 + gates 9,8,7, STS ----
    {
        const int qb = ((t >> 1) << 4) | (t & 1);
        if (first) {
#pragma unroll
            for (int s = 0; s < 8; s++) {
                int q = qb | (s << 1);
                int gp = ((q >> 1) << 11) | (blk << 1) | (q & 1);
                float2 r2 = *(const float2*)&sre[gp << 1];
                float2 i2 = *(const float2*)&sim[gp << 1];
                a[2*s]   = make_float2(r2.x, i2.x);
                a[2*s+1] = make_float2(r2.y, i2.y);
            }
        } else {
#pragma unroll
            for (int s = 0; s < 8; s++) {
                int q = qb | (s << 1);
                int gp = ((q >> 1) << 11) | (blk << 1) | (q & 1);
                float4 v = g_state[gp];
                a[2*s]   = make_float2(v.x, v.y);
                a[2*s+1] = make_float2(v.z, v.w);
            }
        }
        {
            C2 U = getU(layer, 21);
#pragma unroll
            for (int s = 0; s < 8; s++) cgate(a[2*s], a[2*s+1], U);
        }
        gates3(a, layer, 9, 8, 7);
#pragma unroll
        for (int s = 0; s < 8; s++) {
            sh4[sig(qb | (s << 1))] =
                make_float4(a[2*s].x, a[2*s].y, a[2*s+1].x, a[2*s+1].y);
        }
    }
    __syncthreads();

    mid_pass(sh4, t, 4, 6, 5, 4, layer);
    __syncthreads();
    mid_pass(sh4, t, 7, 3, 2, 1, layer);
    __syncthreads();

    // ---- store pass: LDS (s = q bits 8..10), gate qubit 0 on s-bit 2, scatter ----
    {
#pragma unroll
        for (int s = 0; s < 8; s++) {
            float4 v = sh4[sig(t | (s << 8))];
            a[2*s]   = make_float2(v.x, v.y);
            a[2*s+1] = make_float2(v.z, v.w);
        }
        {
            C2 U = getU(layer, 0);
#pragma unroll
            for (int s = 0; s < 8; s++) if (!(s & 4)) {
                cgate(a[2*s],   a[2*(s|4)],   U);
                cgate(a[2*s+1], a[2*(s|4)+1], U);
            }
        }
        const int dA = (t & 3) | (sfx(t) & 0x7FC);
#pragma unroll
        for (int s = 0; s < 8; s++) {
            int dest = dA ^ (sfx(s << 8) & 0x7FC);
            int gp = ((dest >> 1) << 11) | (blk << 1) | (dest & 1);
            g_state[gp] = make_float4(a[2*s].x, a[2*s].y, a[2*s+1].x, a[2*s+1].y);
        }
    }
}

// ---------------------------------------------------------------------------
// Kernel B body: contiguous 2048-pair tile (pair base = blk<<11).
//   q bit j = amp bit j+1 -> qubit 20-j. Gates qubits 10..20 (no intra).
// Pass1 (load, pb=0): 20,19,18. Pass2 (pb=3): 17,16,15. Pass3 (pb=6): 14,13,12.
// Store pass (s = q bits 8..10): qubits 11 (s-bit 1), 10 (s-bit 2).
// Leaves final a[16] in registers (post all gates).
// ---------------------------------------------------------------------------
__device__ __forceinline__ void layerB_body(float4* sh4, float2 a[16], int t,
                                            int base, int layer) {
    {
        const int qb = t << 3;
#pragma unroll
        for (int s = 0; s < 8; s++) {
            float4 v = g_state[base + (qb | s)];
            a[2*s]   = make_float2(v.x, v.y);
            a[2*s+1] = make_float2(v.z, v.w);
        }
        gates3(a, layer, 20, 19, 18);
#pragma unroll
        for (int s = 0; s < 8; s++) {
            sh4[sig(qb | s)] =
                make_float4(a[2*s].x, a[2*s].y, a[2*s+1].x, a[2*s+1].y);
        }
    }
    __syncthreads();
    mid_pass(sh4, t, 3, 17, 16, 15, layer);
    __syncthreads();
    mid_pass(sh4, t, 6, 14, 13, 12, layer);
    __syncthreads();
#pragma unroll
    for (int s = 0; s < 8; s++) {
        float4 v = sh4[sig(t | (s << 8))];
        a[2*s]   = make_float2(v.x, v.y);
        a[2*s+1] = make_float2(v.z, v.w);
    }
    {
        C2 U = getU(layer, 11);
#pragma unroll
        for (int s = 0; s < 8; s++) if (!(s & 2)) {
            cgate(a[2*s],   a[2*(s|2)],   U);
            cgate(a[2*s+1], a[2*(s|2)+1], U);
        }
    }
    {
        C2 U = getU(layer, 10);
#pragma unroll
        for (int s = 0; s < 8; s++) if (!(s & 4)) {
            cgate(a[2*s],   a[2*(s|4)],   U);
            cgate(a[2*s+1], a[2*(s|4)+1], U);
        }
    }
}

// ---------------------------------------------------------------------------
// Kernel B (layers 0..2): store path. CNOTs q=8..20 flip amp bits 0..12 with
// the bit above. In-tile: dest = sfx(q) ^ (bb ? 0x7FF : 0), bb = blk0^blk1;
// dest block: dblk = blk with bit0 ^= bit1 (cross-block scatter);
// half-swap iff dest odd.
// ---------------------------------------------------------------------------
__global__ void __launch_bounds__(256, 4)
layerB_kernel(int layer) {
    extern __shared__ float4 sh4[];
    const int t = threadIdx.x;
    const int blk = blockIdx.x;
    const int base = blk << 11;

    float2 a[16];
    layerB_body(sh4, a, t, base, layer);

    const int sfxt = sfx(t);
    const int bb = (blk ^ (blk >> 1)) & 1;
    const int BB = bb ? 0x7FF : 0;
    const int dbase = (blk ^ ((blk >> 1) & 1)) << 11;
#pragma unroll
    for (int s = 0; s < 8; s++) {
        int dest = sfxt ^ sfx(s << 8) ^ BB;
        float4 v = make_float4(a[2*s].x, a[2*s].y, a[2*s+1].x, a[2*s+1].y);
        if (dest & 1) v = make_float4(v.z, v.w, v.x, v.y);
        g_state[dbase + dest] = v;
    }
}

// ---------------------------------------------------------------------------
// Kernel B last layer: fused <Z> epilogue, no store.
// Final amp: bit0 = c ^ dest0; bits 1..11 = dest; bit12 = blk0^blk1;
// bits 13..21 = blk bits 1..9.  dest = sfx(t)^sfx(s<<8)^BB:
// dest bits 0..8 flip with par(s); bit 9 with s1^s2; bit 10 with s2.
// ---------------------------------------------------------------------------
__global__ void __launch_bounds__(256, 4)
layerB_last_kernel(int layer) {
    extern __shared__ float4 sh4[];
    const int t = threadIdx.x;
    const int blk = blockIdx.x;
    const int base = blk << 11;

    float2 a[16];
    layerB_body(sh4, a, t, base, layer);

    const int sfxt = sfx(t);
    const int bb = (blk ^ (blk >> 1)) & 1;

    float S00 = 0.f, S01 = 0.f, S10 = 0.f, S11 = 0.f, W9 = 0.f, W10 = 0.f;
#pragma unroll
    for (int s = 0; s < 8; s++) {
        float2 x0 = a[2*s], x1 = a[2*s+1];
        float p0 = fmaf(x0.x, x0.x, x0.y * x0.y);
        float p1 = fmaf(x1.x, x1.x, x1.y * x1.y);
        bool par = (0x96 >> s) & 1;          // parity(s)
        if (par) { S10 += p0; S11 += p1; }
        else     { S00 += p0; S01 += p1; }
        float ps = p0 + p1;
        W9  += ((0x3C >> s) & 1) ? -ps : ps; // s1^s2
        W10 += (s & 4) ? -ps : ps;           // s2
    }
    float Se = S00 + S01, So = S10 + S11;
    float T  = Se + So;
    float E  = Se - So;

    float z[13];
    {
        float z0 = (S00 - S01) - (S10 - S11);
        z[0] = (((sfxt ^ bb) & 1)) ? -z0 : z0;          // amp bit 0 (qubit 21)
    }
#pragma unroll
    for (int d = 0; d < 9; d++)                          // amp bits 1..9
        z[d + 1] = ((((sfxt >> d) ^ bb) & 1)) ? -E : E;
    z[10] = bb ? -W9  : W9;                              // amp bit 10 (dest bit 9)
    z[11] = bb ? -W10 : W10;                             // amp bit 11 (dest bit 10)
    z[12] = T;

    __shared__ float wsum[13][9];
    int lane = t & 31, wp = t >> 5;
#pragma unroll
    for (int b = 0; b < 13; b++) {
        float v = z[b];
        for (int off = 16; off; off >>= 1) v += __shfl_xor_sync(0xffffffffu, v, off);
        if (lane == 0) wsum[b][wp] = v;
    }
    __syncthreads();
    if (t < 13) {
        float sacc = 0.f;
        for (int w = 0; w < 8; w++) sacc += wsum[t][w];
        g_zpart[blk][t] = sacc;
    }
}

// ---------------------------------------------------------------------------
// Final reduce: warp w handles qubit w (amp bit b = 21-w). 1024 block partials,
// 32 per lane; warp-shuffle reduce; divide by norm^2 (= total T).
// amp bit 12 sign = blk0^blk1; amp bits 13..21 sign = blk bits 1..9.
// ---------------------------------------------------------------------------
__global__ void final_reduce(float* __restrict__ out) {
    int w = threadIdx.x >> 5;
    int lane = threadIdx.x & 31;
    if (w >= 22) return;
    int b = 21 - w;
    float s = 0.f, tot = 0.f;
#pragma unroll
    for (int k = 0; k < 32; k++) {
        int i = lane + k * 32;
        float Ti = g_zpart[i][12];
        tot += Ti;
        if (b < 12)       s += g_zpart[i][b];
        else if (b == 12) s += (((i ^ (i >> 1)) & 1)) ? -Ti : Ti;
        else              s += (((i >> (b - 12)) & 1)) ? -Ti : Ti;
    }
    for (int off = 16; off; off >>= 1) {
        s   += __shfl_xor_sync(0xffffffffu, s, off);
        tot += __shfl_xor_sync(0xffffffffu, tot, off);
    }
    if (lane == 0) out[w] = s / tot;
}

// ---------------------------------------------------------------------------
extern "C" void kernel_launch(void* const* d_in, const int* in_sizes, int n_in,
                              void* d_out, int out_size) {
    const float* params = (const float*)d_in[0];
    const float* re     = (const float*)d_in[1];
    const float* im     = (const float*)d_in[2];
    float* out = (float*)d_out;

    cudaFuncSetAttribute(layerA_kernel, cudaFuncAttributeMaxDynamicSharedMemorySize, 32768);
    cudaFuncSetAttribute(layerB_kernel, cudaFuncAttributeMaxDynamicSharedMemorySize, 32768);
    cudaFuncSetAttribute(layerB_last_kernel, cudaFuncAttributeMaxDynamicSharedMemorySize, 32768);

    make_gates<<<1, 128>>>(params);
    for (int l = 0; l < NL; l++) {
        layerA_kernel<<<NB, 256, 32768>>>(l, re, im, l == 0 ? 1 : 0);
        if (l < NL - 1) layerB_kernel<<<NB, 256, 32768>>>(l);
        else            layerB_last_kernel<<<NB, 256, 32768>>>(l);
    }
    final_reduce<<<1, 704>>>(out);
}